// round 8
// baseline (speedup 1.0000x reference)
#include <cuda_runtime.h>
#include <cuda_bf16.h>
#include <cstdint>
#include <math.h>

// ---------------------------------------------------------------------------
// RPN head via mma.sync (sm_80+ path, works on plain sm_100 target).
//   x: (16, 512, 64, 96) fp32 NCHW; loc_w (36,512); score_w (18,512)
//   GEMM orientation: A = W (64 outs x 512 ch), B = x (512 ch x positions)
//   Split-bf16 3 terms: D = Ahi*Bhi + Ahi*Blo + Alo*Bhi (fp32 accum)
//   Warp tile: 64 outputs x 32 positions (4 m16 tiles x 4 n8 tiles)
// ---------------------------------------------------------------------------

#define NIMG 16
#define CDIM 512
#define HWP  6144
#define NK16 32              // K chunks of 16
#define POSB 256             // positions per block (8 warps x 32)
#define NWARP 8

#define LOC_TOTAL (NIMG * HWP * 36)
#define SC_TOTAL  (NIMG * HWP * 18)
#define FG_TOTAL  (NIMG * HWP * 9)
#define ANCHOR_OFF (LOC_TOTAL + SC_TOTAL + FG_TOTAL)

#define WF_ITEMS (NK16 * 4 * 2 * 32)   // 8192 uint4 = 128 KB
#define ANC_ITEMS (HWP * 9)            // 55296

// Pre-built A fragments: [kc][tile(4)][term hi/lo][lane(32)] -> uint4 (Ra0..Ra3)
__device__ __align__(16) uint4 g_wfrag[WF_ITEMS];

// ---------------------------------------------------------------------------
// helpers
// ---------------------------------------------------------------------------
// pack two fp32 into bf16x2 (RN); first arg -> high half, second -> low half
__device__ __forceinline__ uint32_t cvt_bf2(float hi_el, float lo_el) {
    uint32_t r;
    asm("cvt.rn.bf16x2.f32 %0, %1, %2;" : "=r"(r) : "f"(hi_el), "f"(lo_el));
    return r;
}

__device__ __forceinline__ void mma_bf16(float* c, const uint4& a,
                                         uint32_t b0, uint32_t b1) {
    asm volatile(
        "mma.sync.aligned.m16n8k16.row.col.f32.bf16.bf16.f32 "
        "{%0,%1,%2,%3}, {%4,%5,%6,%7}, {%8,%9}, {%0,%1,%2,%3};"
        : "+f"(c[0]), "+f"(c[1]), "+f"(c[2]), "+f"(c[3])
        : "r"(a.x), "r"(a.y), "r"(a.z), "r"(a.w), "r"(b0), "r"(b1));
}

// hi/lo bf16x2 for a value pair (f0 -> low element, f1 -> high element)
__device__ __forceinline__ void split_pair(float f0, float f1,
                                           uint32_t& hi, uint32_t& lo) {
    hi = cvt_bf2(f1, f0);
    float h0 = __uint_as_float(hi << 16);
    float h1 = __uint_as_float(hi & 0xFFFF0000u);
    lo = cvt_bf2(f1 - h1, f0 - h0);
}

// ---------------------------------------------------------------------------
// setup: build W hi/lo mma fragments + anchor table
// ---------------------------------------------------------------------------
__device__ __forceinline__ float wval(const float* loc_w, const float* score_w,
                                      int o, int ch) {
    if (o < 36)  return loc_w[o * CDIM + ch];
    if (o < 54)  return score_w[(o - 36) * CDIM + ch];
    return 0.0f;
}
__device__ __forceinline__ uint32_t enc_pair(float f0, float f1, int term) {
    uint32_t hi, lo;
    split_pair(f0, f1, hi, lo);
    return term == 0 ? hi : lo;
}

__global__ void setup_kernel(const float* __restrict__ loc_w,
                             const float* __restrict__ score_w,
                             float* __restrict__ out) {
    int i = blockIdx.x * blockDim.x + threadIdx.x;
    if (i < WF_ITEMS) {
        int lane = i & 31;
        int term = (i >> 5) & 1;
        int t    = (i >> 6) & 3;
        int kc   = i >> 8;
        int o0 = t * 16 + (lane >> 2);
        int c0 = kc * 16 + (lane & 3) * 2;
        uint4 r;
        r.x = enc_pair(wval(loc_w, score_w, o0,     c0),     wval(loc_w, score_w, o0,     c0 + 1), term);
        r.y = enc_pair(wval(loc_w, score_w, o0 + 8, c0),     wval(loc_w, score_w, o0 + 8, c0 + 1), term);
        r.z = enc_pair(wval(loc_w, score_w, o0,     c0 + 8), wval(loc_w, score_w, o0,     c0 + 9), term);
        r.w = enc_pair(wval(loc_w, score_w, o0 + 8, c0 + 8), wval(loc_w, score_w, o0 + 8, c0 + 9), term);
        g_wfrag[i] = r;
    }
    int j = i - WF_ITEMS;
    if (j >= 0 && j < ANC_ITEMS) {
        int hw = j / 9, a = j - hw * 9;
        int h = hw / 96, w = hw - h * 96;
        const double ratios[3] = {0.5, 1.0, 2.0};
        const double scales[3] = {8.0, 16.0, 32.0};
        double r = ratios[a / 3], s = scales[a % 3];
        double bh = 16.0 * s * sqrt(r), bw = 16.0 * s * sqrt(1.0 / r);
        float sy = (float)(h * 16), sx = (float)(w * 16);
        float4 res;
        res.x = sy + (float)(8.0 - bh * 0.5);
        res.y = sx + (float)(8.0 - bw * 0.5);
        res.z = sy + (float)(8.0 + bh * 0.5);
        res.w = sx + (float)(8.0 + bw * 0.5);
        *(float4*)(out + ANCHOR_OFF + (size_t)j * 4) = res;
    }
}

// ---------------------------------------------------------------------------
// main kernel: 256 threads (8 warps), 256 positions/block
// warp: 32 positions (four n8 tiles) x 64 outputs (four m16 tiles)
// ---------------------------------------------------------------------------
__global__ __launch_bounds__(256, 2)
void rpn_mma_kernel(const float* __restrict__ x,
                    const float* __restrict__ loc_b,
                    const float* __restrict__ score_b,
                    float* __restrict__ out) {
    __shared__ float sm[128 * 66];
    __shared__ float sb[64];

    const int tid  = threadIdx.x;
    const int lane = tid & 31;
    const int warp = tid >> 5;
    const int n    = blockIdx.y;
    const int pblk = blockIdx.x * POSB;

    if (tid < 64)
        sb[tid] = (tid < 36) ? loc_b[tid] : ((tid < 54) ? score_b[tid - 36] : 0.0f);

    const int pw   = pblk + warp * 32;        // warp's 32 positions
    const int prow = lane >> 2;               // position within octet (B frag col)
    const int kch  = (lane & 3) * 2;          // channel offset within k16 (B frag row)

    const float* xp = x + (size_t)n * CDIM * HWP + (size_t)kch * HWP + pw + prow;
    const uint4* wf = g_wfrag + lane;

    float acc[4][4][4];                       // [m tile][n tile u][frag reg]
#pragma unroll
    for (int t = 0; t < 4; t++)
#pragma unroll
        for (int u = 0; u < 4; u++)
#pragma unroll
            for (int r = 0; r < 4; r++) acc[t][u][r] = 0.0f;

    // x fragment values: [u][0]=ch, [1]=ch+1, [2]=ch+8, [3]=ch+9 at pos u*8+prow
    float xf[4][4];
#pragma unroll
    for (int u = 0; u < 4; u++) {
        const float* b = xp + u * 8;
        xf[u][0] = __ldcs(b);
        xf[u][1] = __ldcs(b + HWP);
        xf[u][2] = __ldcs(b + 8 * HWP);
        xf[u][3] = __ldcs(b + 9 * HWP);
    }

    for (int kc = 0; kc < NK16; kc++) {
        // split current x into bf16 hi/lo B fragments (xf dead afterwards)
        uint32_t Bhi[4][2], Blo[4][2];
#pragma unroll
        for (int u = 0; u < 4; u++) {
            split_pair(xf[u][0], xf[u][1], Bhi[u][0], Blo[u][0]);
            split_pair(xf[u][2], xf[u][3], Bhi[u][1], Blo[u][1]);
        }

        // prefetch next chunk's x into xf (latency hidden by the mma tail)
        xp += 16 * HWP;
        if (kc + 1 < NK16) {
#pragma unroll
            for (int u = 0; u < 4; u++) {
                const float* b = xp + u * 8;
                xf[u][0] = __ldcs(b);
                xf[u][1] = __ldcs(b + HWP);
                xf[u][2] = __ldcs(b + 8 * HWP);
                xf[u][3] = __ldcs(b + 9 * HWP);
            }
        }

        const uint4* wfk = wf + kc * 256;
#pragma unroll
        for (int t = 0; t < 4; t++) {
            uint4 ah = __ldg(wfk + t * 64);        // hi term fragment
            uint4 al = __ldg(wfk + t * 64 + 32);   // lo term fragment
#pragma unroll
            for (int u = 0; u < 4; u++) {
                mma_bf16(acc[t][u], ah, Bhi[u][0], Bhi[u][1]);
                mma_bf16(acc[t][u], ah, Blo[u][0], Blo[u][1]);
                mma_bf16(acc[t][u], al, Bhi[u][0], Bhi[u][1]);
            }
        }
    }

    // ---- epilogue in two waves of 128 positions (reuse 34 KB smem) ----
    const int plb = (warp & 3) * 32 + (lane & 3) * 2;  // pos base within wave
    const int oc  = lane >> 2;
#pragma unroll
    for (int w = 0; w < 2; w++) {
        if ((warp >> 2) == w) {
#pragma unroll
            for (int t = 0; t < 4; t++)
#pragma unroll
                for (int u = 0; u < 4; u++) {
                    float* r0 = sm + (plb + u * 8) * 66 + t * 16 + oc;
                    float* r1 = sm + (plb + u * 8 + 1) * 66 + t * 16 + oc;
                    r0[0] = acc[t][u][0];
                    r1[0] = acc[t][u][1];
                    r0[8] = acc[t][u][2];
                    r1[8] = acc[t][u][3];
                }
        }
        __syncthreads();

        const int pos = tid >> 1;
        const int hw  = pblk + w * 128 + pos;
        const float* row = sm + pos * 66;
        if ((tid & 1) == 0) {
            float* dl = out + ((size_t)n * HWP + hw) * 36;
#pragma unroll
            for (int j = 0; j < 9; j++) {
                float4 v;
                v.x = row[4 * j]     + sb[4 * j];
                v.y = row[4 * j + 1] + sb[4 * j + 1];
                v.z = row[4 * j + 2] + sb[4 * j + 2];
                v.w = row[4 * j + 3] + sb[4 * j + 3];
                *(float4*)(dl + 4 * j) = v;
            }
        } else {
            float s[18];
#pragma unroll
            for (int j = 0; j < 18; j++) s[j] = row[36 + j] + sb[36 + j];
            float* ds = out + LOC_TOTAL + ((size_t)n * HWP + hw) * 18;
#pragma unroll
            for (int j = 0; j < 9; j++)
                *(float2*)(ds + 2 * j) = make_float2(s[2 * j], s[2 * j + 1]);
            float* df = out + LOC_TOTAL + SC_TOTAL + ((size_t)n * HWP + hw) * 9;
#pragma unroll
            for (int a = 0; a < 9; a++)
                df[a] = 1.0f / (1.0f + __expf(s[2 * a] - s[2 * a + 1]));
        }
        if (w == 0) __syncthreads();
    }
}

// ---------------------------------------------------------------------------
// launch: inputs x, loc_w, loc_b, score_w, score_b
// output (float32 concat): rpn_loc | rpn_score | rpn_fg_scores | anchor
// ---------------------------------------------------------------------------
extern "C" void kernel_launch(void* const* d_in, const int* in_sizes, int n_in,
                              void* d_out, int out_size) {
    (void)in_sizes; (void)n_in; (void)out_size;
    const float* x       = (const float*)d_in[0];
    const float* loc_w   = (const float*)d_in[1];
    const float* loc_b   = (const float*)d_in[2];
    const float* score_w = (const float*)d_in[3];
    const float* score_b = (const float*)d_in[4];
    float* out = (float*)d_out;

    setup_kernel<<<(WF_ITEMS + ANC_ITEMS + 255) / 256, 256>>>(loc_w, score_w, out);

    dim3 grid(HWP / POSB, NIMG);  // (24, 16) = 384 blocks
    rpn_mma_kernel<<<grid, 256>>>(x, loc_b, score_b, out);
}